// round 9
// baseline (speedup 1.0000x reference)
#include <cuda_runtime.h>
#include <math.h>
#include <stdint.h>

// PointLoss_like_GPS — GB300 sm_103a, Round 9
// Windowed-smem pruned NN: 512 small searcher blocks stage only their own
// x-window (<=24KB) in dynamic smem; rare out-of-window expansion reads L2.
// Exact pruning bounds (validated R6-R8), two-kernel structure.

#define NPTS    4096
#define NBUCK   64
#define XMIN    (-3.0f)
#define BW      (6.0f / NBUCK)      /* 3/32 exact; k*BW exact for k<=64 */
#define MAXSETS 8
#define ATHR    512                 /* bucket kernel threads */
#define STHR    64                  /* searcher block threads (2 warps) */
#define QPB     64                  /* queries per searcher block */
#define BPP     (NPTS / QPB)        /* 64 searcher blocks per pair */
#define MARGIN  5                   /* window margin in buckets per side */
#define SMCAP   2080                /* smem window capacity (points), mult of 4 */

__device__ float        g_sx[MAXSETS][NPTS];
__device__ float        g_sy[MAXSETS][NPTS];
__device__ float        g_sz[MAXSETS][NPTS];
__device__ int          g_bstart[MAXSETS][NBUCK + 1];
__device__ float        g_partials[MAXSETS * BPP];
__device__ unsigned int g_ticket;

__device__ __forceinline__ int bucket_of(float x)
{
    int b = (int)floorf((x - XMIN) * (1.0f / BW));
    return min(max(b, 0), NBUCK - 1);
}

__device__ __forceinline__ float2 addf32x2(unsigned long long a, unsigned long long b)
{
    float2 r;
    asm("{\n\t"
        ".reg .b64 t;\n\t"
        "add.rn.f32x2 t, %2, %3;\n\t"
        "mov.b64 {%0, %1}, t;\n\t"
        "}"
        : "=f"(r.x), "=f"(r.y) : "l"(a), "l"(b));
    return r;
}

__device__ __forceinline__ unsigned long long bcast2(float v)
{
    unsigned long long r;
    asm("mov.b64 %0, {%1, %1};" : "=l"(r) : "f"(v));
    return r;
}

// smem scan over global sorted idx [a,b); smem holds [S4, E4) at offset -S4.
// 4-group alignment slop scans real in-window/adjacent points (idempotent).
__device__ __forceinline__ void scan_smem(
    const float* shX, const float* shY, const float* shZ, int S4,
    int a, int b,
    unsigned long long nqx2, unsigned long long nqy2, unsigned long long nqz2,
    float& dm0, float& dm1, float& dm2, float& dm3)
{
    const double2* X = (const double2*)shX;
    const double2* Y = (const double2*)shY;
    const double2* Z = (const double2*)shZ;
    const int g0 = (a - S4) >> 2;
    const int g1 = ((b - S4) + 3) >> 2;

    #pragma unroll 2
    for (int g = g0; g < g1; ++g) {
        const double2 xv = X[g], yv = Y[g], zv = Z[g];

        const float2 dx01 = addf32x2(__double_as_longlong(xv.x), nqx2);
        const float2 dx23 = addf32x2(__double_as_longlong(xv.y), nqx2);
        const float2 dy01 = addf32x2(__double_as_longlong(yv.x), nqy2);
        const float2 dy23 = addf32x2(__double_as_longlong(yv.y), nqy2);
        const float2 dz01 = addf32x2(__double_as_longlong(zv.x), nqz2);
        const float2 dz23 = addf32x2(__double_as_longlong(zv.y), nqz2);

        const float s0 = (fabsf(dx01.x) + fabsf(dy01.x)) + fabsf(dz01.x);
        const float s1 = (fabsf(dx01.y) + fabsf(dy01.y)) + fabsf(dz01.y);
        const float s2 = (fabsf(dx23.x) + fabsf(dy23.x)) + fabsf(dz23.x);
        const float s3 = (fabsf(dx23.y) + fabsf(dy23.y)) + fabsf(dz23.y);

        dm0 = fminf(dm0, s0);
        dm1 = fminf(dm1, s1);
        dm2 = fminf(dm2, s2);
        dm3 = fminf(dm3, s3);
    }
}

// global fallback scan (rare): warp-uniform L2 broadcast loads
__device__ __forceinline__ void scan_glob(
    const float* gx, const float* gy, const float* gz,
    int a, int b, float qx, float qy, float qz, float& dm0)
{
    for (int j = a; j < b; ++j) {
        const float d = fabsf(qx - __ldg(&gx[j]))
                      + fabsf(qy - __ldg(&gy[j]))
                      + fabsf(qz - __ldg(&gz[j]));
        dm0 = fminf(dm0, d);
    }
}

// ---------------- Kernel A: bucket sort into SoA ----------------------------
__global__ void __launch_bounds__(ATHR)
bucket_kernel(const float* __restrict__ a1, const float* __restrict__ a2)
{
    __shared__ int hist[NBUCK];
    __shared__ int cur[NBUCK];

    const int s   = blockIdx.x;
    const int tid = threadIdx.x;
    if (s == 0 && tid == 0) g_ticket = 0;

    const int bb = s >> 1;
    const float* base = ((s & 1) ? a2 : a1) + (size_t)bb * NPTS * 3;

    if (tid < NBUCK) hist[tid] = 0;
    __syncthreads();

    for (int i = tid; i < NPTS; i += ATHR)
        atomicAdd(&hist[bucket_of(base[i * 3])], 1);
    __syncthreads();

    if (tid == 0) {
        int acc = 0;
        for (int k = 0; k < NBUCK; k++) {
            cur[k] = acc;
            g_bstart[s][k] = acc;
            acc += hist[k];
        }
        g_bstart[s][NBUCK] = acc;
    }
    __syncthreads();

    for (int i = tid; i < NPTS; i += ATHR) {
        const float x = base[i * 3 + 0];
        const float y = base[i * 3 + 1];
        const float z = base[i * 3 + 2];
        const int pos = atomicAdd(&cur[bucket_of(x)], 1);
        g_sx[s][pos] = x;
        g_sy[s][pos] = y;
        g_sz[s][pos] = z;
    }
}

// ---------------- Kernel B: windowed-smem NN search -------------------------
__global__ void __launch_bounds__(STHR)
search_kernel(const float* __restrict__ alpha_p,
              const float* __restrict__ beta_p,
              float* __restrict__ out,
              int nblocks, float scale)
{
    extern __shared__ __align__(16) float dyn[];   // 3 * SMCAP floats
    __shared__ float red[2];
    __shared__ int s_win[3];                       // S4, E, use_smem

    const int tid = threadIdx.x;
    const int bx  = blockIdx.x;
    const int bl  = bx & (BPP - 1);                // block within pair
    const int p   = bx / BPP;                      // pair
    const int bb  = p >> 1;
    const int sset = (p & 1) ? (2 * bb) : (2 * bb + 1);
    const int rset = sset ^ 1;

    const int* bst = g_bstart[rset];
    const int Q0   = bl * QPB;

    // block window: buckets of first/last query +- MARGIN
    if (tid == 0) {
        const int qb0 = bucket_of(g_sx[sset][Q0]);
        const int qb1 = bucket_of(g_sx[sset][Q0 + QPB - 1]);
        int wlo = max(qb0 - MARGIN, 0);
        int whi = min(qb1 + MARGIN, NBUCK - 1);
        int S   = __ldg(&bst[wlo]);
        int E   = __ldg(&bst[whi + 1]);
        // shrink margins if window exceeds capacity (statistically never)
        while ((((E + 3) & ~3) - (S & ~3)) > SMCAP && (wlo < qb0 || whi > qb1)) {
            if (wlo < qb0) ++wlo;
            if (whi > qb1) --whi;
            S = __ldg(&bst[wlo]);
            E = __ldg(&bst[whi + 1]);
        }
        const int S4 = S & ~3;
        const int ok = ((((E + 3) & ~3) - S4) <= SMCAP) ? 1 : 0;
        s_win[0] = S4;
        s_win[1] = E;
        s_win[2] = ok;
    }
    __syncthreads();

    const int S4       = s_win[0];
    const int E        = s_win[1];
    const int use_smem = s_win[2];
    const int E4       = (E + 3) & ~3;
    const int S        = S4;       // smem holds [S4, E4); containment vs S4 is
                                   // looser than vs S and all pts are real refs

    float* shX = dyn;
    float* shY = dyn + SMCAP;
    float* shZ = dyn + 2 * SMCAP;

    const float* gx = g_sx[rset];
    const float* gy = g_sy[rset];
    const float* gz = g_sz[rset];

    if (use_smem) {
        const int ng = (E4 - S4) >> 2;             // float4 groups
        const float4* gx4 = (const float4*)(gx + S4);
        const float4* gy4 = (const float4*)(gy + S4);
        const float4* gz4 = (const float4*)(gz + S4);
        for (int i = tid; i < ng; i += STHR) {
            ((float4*)shX)[i] = gx4[i];
            ((float4*)shY)[i] = gy4[i];
            ((float4*)shZ)[i] = gz4[i];
        }
    }
    __syncthreads();

    const int w    = tid >> 5;
    const int lane = tid & 31;
    const int q    = Q0 + w * 32 + lane;

    const float qx = g_sx[sset][q];
    const float qy = g_sy[sset][q];
    const float qz = g_sz[sset][q];

    const unsigned long long nqx2 = bcast2(-qx);
    const unsigned long long nqy2 = bcast2(-qy);
    const unsigned long long nqz2 = bcast2(-qz);

    const int myb = bucket_of(qx);
    int blo = __shfl_sync(0xffffffffu, myb, 0);
    int bhi = __shfl_sync(0xffffffffu, myb, 31);

    float dm0 = 3.402823466e38f, dm1 = dm0, dm2 = dm0, dm3 = dm0;

    // initial scan: warp's own bucket span (always inside window when use_smem)
    {
        const int a = __ldg(&bst[blo]);
        const int b = __ldg(&bst[bhi + 1]);
        if (use_smem && a >= S && b <= E)
            scan_smem(shX, shY, shZ, S4, a, b, nqx2, nqy2, nqz2, dm0, dm1, dm2, dm3);
        else
            scan_glob(gx, gy, gz, a, b, qx, qy, qz, dm0);
    }

    // expand until every lane's dmin is provably final (exact fp32 edges)
    while (true) {
        const float dcur = fminf(fminf(dm0, dm1), fminf(dm2, dm3));
        const bool lok = (blo == 0) ||
                         (dcur <= qx - (XMIN + (float)blo * BW));
        const bool rok = (bhi == NBUCK - 1) ||
                         (dcur <= (XMIN + (float)(bhi + 1) * BW) - qx);
        if (__all_sync(0xffffffffu, lok && rok)) break;

        const int nlo = max(blo - 1, 0);
        const int nhi = min(bhi + 1, NBUCK - 1);
        if (nlo == blo && nhi == bhi) break;       // full coverage

        if (nlo < blo) {
            const int a = __ldg(&bst[nlo]);
            const int b = __ldg(&bst[blo]);
            if (use_smem && a >= S && b <= E)
                scan_smem(shX, shY, shZ, S4, a, b, nqx2, nqy2, nqz2, dm0, dm1, dm2, dm3);
            else
                scan_glob(gx, gy, gz, a, b, qx, qy, qz, dm0);
        }
        if (nhi > bhi) {
            const int a = __ldg(&bst[bhi + 1]);
            const int b = __ldg(&bst[nhi + 1]);
            if (use_smem && a >= S && b <= E)
                scan_smem(shX, shY, shZ, S4, a, b, nqx2, nqy2, nqz2, dm0, dm1, dm2, dm3);
            else
                scan_glob(gx, gy, gz, a, b, qx, qy, qz, dm0);
        }
        blo = nlo; bhi = nhi;
    }

    const float dmin = fminf(fminf(dm0, dm1), fminf(dm2, dm3));

    const float alpha = *alpha_p;
    const float beta  = *beta_p;
    const float delta = __powf(alpha, -1.0f / beta);
    const float sv = alpha * __powf(dmin, beta) + delta;
    float v = -sv * __expf(-sv);

    #pragma unroll
    for (int o = 16; o > 0; o >>= 1)
        v += __shfl_down_sync(0xffffffffu, v, o);
    if (lane == 0) red[w] = v;
    __syncthreads();

    if (tid == 0) {
        g_partials[bx] = red[0] + red[1];
        __threadfence();
        const unsigned int t = atomicAdd(&g_ticket, 1u);
        if (t == (unsigned)(nblocks - 1)) {
            float total = 0.0f;
            for (int r = 0; r < nblocks; r++)
                total += *((volatile float*)&g_partials[r]);
            out[0] = total * scale;
        }
    }
}

extern "C" void kernel_launch(void* const* d_in, const int* in_sizes, int n_in,
                              void* d_out, int out_size)
{
    const float* a1    = (const float*)d_in[0];
    const float* a2    = (const float*)d_in[1];
    const float* alpha = (const float*)d_in[2];
    const float* beta  = (const float*)d_in[3];
    float* out = (float*)d_out;

    const int B       = in_sizes[0] / (NPTS * 3);
    const int nsets   = 2 * B;                 // 8
    const int nblocks = nsets * BPP;           // 512
    const float scale = 50.0f / (float)B;

    const int smem = 3 * SMCAP * (int)sizeof(float);   // ~24.4 KB
    cudaFuncSetAttribute(search_kernel,
                         cudaFuncAttributeMaxDynamicSharedMemorySize, smem);

    bucket_kernel<<<nsets, ATHR>>>(a1, a2);
    search_kernel<<<nblocks, STHR, smem>>>(alpha, beta, out, nblocks, scale);
}

// round 10
// speedup vs baseline: 1.8083x; 1.8083x over previous
#include <cuda_runtime.h>
#include <math.h>
#include <stdint.h>

// PointLoss_like_GPS — GB300 sm_103a, Round 10
// Pruned NN with manufactured parallelism: 128-thr blocks, 32 sorted queries
// per block (query = lane, shared by all 4 warps), warps scan disjoint
// quarters of the block's staged x-window; cross-warp smem min; exact bound
// check; rare exact fallback = full-set scan split across the 4 warps.

#define NPTS    4096
#define NBUCK   64
#define XMIN    (-3.0f)
#define BW      (6.0f / NBUCK)      /* 3/32 exact; k*BW exact for k<=64 */
#define MAXSETS 8
#define ATHR    512
#define STHR    128
#define QPB     32
#define BPP     (NPTS / QPB)        /* 128 searcher blocks per pair */
#define MARGIN  4
#define SMCAP   2048                /* staged window capacity (points) */

__device__ __align__(16) float g_sx[MAXSETS][NPTS];
__device__ __align__(16) float g_sy[MAXSETS][NPTS];
__device__ __align__(16) float g_sz[MAXSETS][NPTS];
__device__ int          g_bstart[MAXSETS][NBUCK + 1];
__device__ float        g_partials[MAXSETS * BPP];   // 1024
__device__ unsigned int g_ticket;

__device__ __forceinline__ int bucket_of(float x)
{
    int b = (int)floorf((x - XMIN) * (1.0f / BW));
    return min(max(b, 0), NBUCK - 1);
}

__device__ __forceinline__ float2 addf32x2(unsigned long long a, unsigned long long b)
{
    float2 r;
    asm("{\n\t"
        ".reg .b64 t;\n\t"
        "add.rn.f32x2 t, %2, %3;\n\t"
        "mov.b64 {%0, %1}, t;\n\t"
        "}"
        : "=f"(r.x), "=f"(r.y) : "l"(a), "l"(b));
    return r;
}

__device__ __forceinline__ unsigned long long bcast2(float v)
{
    unsigned long long r;
    asm("mov.b64 %0, {%1, %1};" : "=l"(r) : "f"(v));
    return r;
}

// scan 4-ref groups [gA, gB) from double2-viewable SoA arrays
__device__ __forceinline__ void scan_groups(
    const double2* __restrict__ X, const double2* __restrict__ Y,
    const double2* __restrict__ Z, int gA, int gB,
    unsigned long long nqx2, unsigned long long nqy2, unsigned long long nqz2,
    float& dm0, float& dm1, float& dm2, float& dm3)
{
    #pragma unroll 4
    for (int g = gA; g < gB; ++g) {
        const double2 xv = X[g], yv = Y[g], zv = Z[g];

        const float2 dx01 = addf32x2(__double_as_longlong(xv.x), nqx2);
        const float2 dx23 = addf32x2(__double_as_longlong(xv.y), nqx2);
        const float2 dy01 = addf32x2(__double_as_longlong(yv.x), nqy2);
        const float2 dy23 = addf32x2(__double_as_longlong(yv.y), nqy2);
        const float2 dz01 = addf32x2(__double_as_longlong(zv.x), nqz2);
        const float2 dz23 = addf32x2(__double_as_longlong(zv.y), nqz2);

        const float s0 = (fabsf(dx01.x) + fabsf(dy01.x)) + fabsf(dz01.x);
        const float s1 = (fabsf(dx01.y) + fabsf(dy01.y)) + fabsf(dz01.y);
        const float s2 = (fabsf(dx23.x) + fabsf(dy23.x)) + fabsf(dz23.x);
        const float s3 = (fabsf(dx23.y) + fabsf(dy23.y)) + fabsf(dz23.y);

        dm0 = fminf(dm0, s0);
        dm1 = fminf(dm1, s1);
        dm2 = fminf(dm2, s2);
        dm3 = fminf(dm3, s3);
    }
}

// ---------------- Kernel A: bucket sort (warp-scan prefix) ------------------
__global__ void __launch_bounds__(ATHR)
bucket_kernel(const float* __restrict__ a1, const float* __restrict__ a2)
{
    __shared__ int hist[NBUCK];
    __shared__ int cur[NBUCK];

    const int s   = blockIdx.x;
    const int tid = threadIdx.x;
    if (s == 0 && tid == 0) g_ticket = 0;    // reset before search launches

    const int bb = s >> 1;
    const float* base = ((s & 1) ? a2 : a1) + (size_t)bb * NPTS * 3;

    if (tid < NBUCK) hist[tid] = 0;
    __syncthreads();

    for (int i = tid; i < NPTS; i += ATHR)
        atomicAdd(&hist[bucket_of(base[i * 3])], 1);
    __syncthreads();

    if (tid < 32) {
        const int h0 = hist[tid], h1 = hist[tid + 32];
        int v0 = h0, v1 = h1;
        #pragma unroll
        for (int o = 1; o < 32; o <<= 1) {
            int t0 = __shfl_up_sync(0xffffffffu, v0, o);
            int t1 = __shfl_up_sync(0xffffffffu, v1, o);
            if (tid >= o) { v0 += t0; v1 += t1; }
        }
        const int tot0 = __shfl_sync(0xffffffffu, v0, 31);
        const int tot1 = __shfl_sync(0xffffffffu, v1, 31);
        const int e0 = v0 - h0;
        const int e1 = v1 - h1 + tot0;
        cur[tid] = e0;           cur[tid + 32] = e1;
        g_bstart[s][tid] = e0;   g_bstart[s][tid + 32] = e1;
        if (tid == 0) g_bstart[s][NBUCK] = tot0 + tot1;
    }
    __syncthreads();

    for (int i = tid; i < NPTS; i += ATHR) {
        const float x = base[i * 3 + 0];
        const float y = base[i * 3 + 1];
        const float z = base[i * 3 + 2];
        const int pos = atomicAdd(&cur[bucket_of(x)], 1);
        g_sx[s][pos] = x;
        g_sy[s][pos] = y;
        g_sz[s][pos] = z;
    }
}

// ---------------- Kernel B: 4-warps-per-32-queries pruned search ------------
__global__ void __launch_bounds__(STHR, 8)
search_kernel(const float* __restrict__ alpha_p,
              const float* __restrict__ beta_p,
              float* __restrict__ out,
              int nblocks, float scale)
{
    extern __shared__ __align__(16) float dyn[];   // 3 * SMCAP floats
    __shared__ float sdm[STHR];
    __shared__ float red[2];
    __shared__ int   swin[3];                      // S4, ng, flags(wlo|whi|ok)
    __shared__ int   sflag;

    const int tid  = threadIdx.x;
    const int lane = tid & 31;
    const int w    = tid >> 5;
    const int bx   = blockIdx.x;
    const int bl   = bx & (BPP - 1);
    const int p    = bx / BPP;
    const int bb   = p >> 1;
    const int sset = (p & 1) ? (2 * bb) : (2 * bb + 1);
    const int rset = sset ^ 1;

    const int* bst = g_bstart[rset];
    const int Q0   = bl * QPB;

    if (tid == 0) {
        const int qb0 = bucket_of(g_sx[sset][Q0]);
        const int qb1 = bucket_of(g_sx[sset][Q0 + QPB - 1]);
        const int wlo = max(qb0 - MARGIN, 0);
        const int whi = min(qb1 + MARGIN, NBUCK - 1);
        const int S4  = bst[wlo] & ~3;
        const int E4  = (bst[whi + 1] + 3) & ~3;
        const int ok  = ((E4 - S4) <= SMCAP) ? 1 : 0;
        swin[0] = S4;
        swin[1] = (E4 - S4) >> 2;                  // groups
        swin[2] = wlo | (whi << 8) | (ok << 16);
        sflag   = 0;
    }
    __syncthreads();

    const int S4  = swin[0];
    const int ng  = swin[1];
    const int wlo = swin[2] & 0xff;
    const int whi = (swin[2] >> 8) & 0xff;
    const int ok  = (swin[2] >> 16) & 1;

    const float* gx = g_sx[rset];
    const float* gy = g_sy[rset];
    const float* gz = g_sz[rset];

    float* shX = dyn;
    float* shY = dyn + SMCAP;
    float* shZ = dyn + 2 * SMCAP;

    if (ok) {
        const float4* gx4 = (const float4*)(gx + S4);
        const float4* gy4 = (const float4*)(gy + S4);
        const float4* gz4 = (const float4*)(gz + S4);
        for (int i = tid; i < ng; i += STHR) {
            ((float4*)shX)[i] = gx4[i];
            ((float4*)shY)[i] = gy4[i];
            ((float4*)shZ)[i] = gz4[i];
        }
    }
    __syncthreads();

    const int q  = Q0 + lane;                      // query = lane (all warps)
    const float qx = g_sx[sset][q];
    const float qy = g_sy[sset][q];
    const float qz = g_sz[sset][q];

    const unsigned long long nqx2 = bcast2(-qx);
    const unsigned long long nqy2 = bcast2(-qy);
    const unsigned long long nqz2 = bcast2(-qz);

    float dm0 = 3.402823466e38f, dm1 = dm0, dm2 = dm0, dm3 = dm0;

    if (ok) {
        // warp w scans its contiguous quarter of the staged window
        const int gA = (w * ng) >> 2;
        const int gB = ((w + 1) * ng) >> 2;
        scan_groups((const double2*)shX, (const double2*)shY,
                    (const double2*)shZ, gA, gB,
                    nqx2, nqy2, nqz2, dm0, dm1, dm2, dm3);
    } else {
        // capacity overflow (statistically never): exact full-set scan, split
        scan_groups((const double2*)gx, (const double2*)gy,
                    (const double2*)gz, w * (NPTS / 4 / 4), (w + 1) * (NPTS / 4 / 4),
                    nqx2, nqy2, nqz2, dm0, dm1, dm2, dm3);
    }

    sdm[tid] = fminf(fminf(dm0, dm1), fminf(dm2, dm3));
    __syncthreads();

    float dmin = fminf(fminf(sdm[lane], sdm[32 + lane]),
                       fminf(sdm[64 + lane], sdm[96 + lane]));

    if (ok) {
        // exact bound: unscanned refs differ in x by at least the edge gap
        const bool lok = (wlo == 0) ||
                         (dmin <= qx - (XMIN + (float)wlo * BW));
        const bool rok = (whi == NBUCK - 1) ||
                         (dmin <= (XMIN + (float)(whi + 1) * BW) - qx);
        if (!(lok && rok)) sflag = 1;
    }
    __syncthreads();

    if (sflag && ok) {
        // rare exact fallback: full-set scan split across the 4 warps
        scan_groups((const double2*)gx, (const double2*)gy,
                    (const double2*)gz, w * (NPTS / 4 / 4), (w + 1) * (NPTS / 4 / 4),
                    nqx2, nqy2, nqz2, dm0, dm1, dm2, dm3);
        sdm[tid] = fminf(fminf(dm0, dm1), fminf(dm2, dm3));
        __syncthreads();
        dmin = fminf(fminf(sdm[lane], sdm[32 + lane]),
                     fminf(sdm[64 + lane], sdm[96 + lane]));
    }

    // epilogue + reduction: warp 0 owns the block's 32 queries
    if (w == 0) {
        const float alpha = *alpha_p;
        const float beta  = *beta_p;
        const float delta = __powf(alpha, -1.0f / beta);
        const float sv = alpha * __powf(dmin, beta) + delta;
        float v = -sv * __expf(-sv);

        #pragma unroll
        for (int o = 16; o > 0; o >>= 1)
            v += __shfl_down_sync(0xffffffffu, v, o);

        if (lane == 0) {
            g_partials[bx] = v;
            __threadfence();
            const unsigned int t = atomicAdd(&g_ticket, 1u);
            red[0] = (t == (unsigned)(nblocks - 1)) ? 1.0f : 0.0f;
        }
    }
    __syncthreads();

    if (red[0] != 0.0f) {
        float acc = 0.0f;
        for (int i = tid; i < nblocks; i += STHR)
            acc += *((volatile float*)&g_partials[i]);
        #pragma unroll
        for (int o = 16; o > 0; o >>= 1)
            acc += __shfl_down_sync(0xffffffffu, acc, o);
        if (lane == 0) sdm[w] = acc;
        __syncthreads();
        if (tid == 0)
            out[0] = (sdm[0] + sdm[1] + sdm[2] + sdm[3]) * scale;
    }
}

extern "C" void kernel_launch(void* const* d_in, const int* in_sizes, int n_in,
                              void* d_out, int out_size)
{
    const float* a1    = (const float*)d_in[0];
    const float* a2    = (const float*)d_in[1];
    const float* alpha = (const float*)d_in[2];
    const float* beta  = (const float*)d_in[3];
    float* out = (float*)d_out;

    const int B       = in_sizes[0] / (NPTS * 3);
    const int nsets   = 2 * B;                 // 8
    const int nblocks = nsets * BPP;           // 1024
    const float scale = 50.0f / (float)B;

    const int smem = 3 * SMCAP * (int)sizeof(float);   // 24 KB
    cudaFuncSetAttribute(search_kernel,
                         cudaFuncAttributeMaxDynamicSharedMemorySize, smem);

    bucket_kernel<<<nsets, ATHR>>>(a1, a2);
    search_kernel<<<nblocks, STHR, smem>>>(alpha, beta, out, nblocks, scale);
}

// round 11
// speedup vs baseline: 4.1600x; 2.3005x over previous
#include <cuda_runtime.h>
#include <cuda_fp16.h>
#include <math.h>
#include <stdint.h>

// PointLoss_like_GPS — GB300 sm_103a, Round 11
// R5 skeleton (ref-split brute force, proven 39.4us) with the inner distance
// engine switched to fp16x2: 2 ref points packed per half2 register.
// Per 2 pts: 3 HSUB2 + 3 HABS2 + 2 HADD2 + 1 HMIN2  (fma 5 vs fp32's 7).
// Precision: dmin abs err ~1e-3 -> final loss rel err ~5e-5 << 1e-3 gate.

#define NPTS    4096
#define DIMS    3
#define THREADS 256
#define SPLITS  8
#define RSPLIT  (NPTS / SPLITS)      // 512 refs per block
#define MAXQ    32768                // 2B*N at B=4
#define FINB    8                    // finalizer blocks

__device__ float        g_dmin[MAXQ * SPLITS];  // layout [q][split]
__device__ float        g_fpart[FINB];
__device__ unsigned int g_ticket1;
__device__ unsigned int g_ticket2;

__device__ __forceinline__ __half2 h2_of(unsigned int u)
{
    return *reinterpret_cast<const __half2*>(&u);
}

__global__ void __launch_bounds__(THREADS, 6)
gps_kernel(const float* __restrict__ a1,
           const float* __restrict__ a2,
           const float* __restrict__ alpha_p,
           const float* __restrict__ beta_p,
           float* __restrict__ out,
           int nq, int nblocks, float scale)
{
    __shared__ __align__(16) __half2 shX[RSPLIT / 2];   // 512 pts = 256 half2
    __shared__ __align__(16) __half2 shY[RSPLIT / 2];
    __shared__ __align__(16) __half2 shZ[RSPLIT / 2];
    __shared__ float red[THREADS / 32];
    __shared__ unsigned int s_ticket;

    const int tid = threadIdx.x;
    const int bx  = blockIdx.x;

    // bx = pair*(16*SPLITS) + qc*SPLITS + sp
    const int sp   = bx & (SPLITS - 1);
    const int qc   = (bx >> 3) & 15;
    const int pair = bx >> 7;
    const int q    = (qc << 8) + tid;
    const int b    = pair >> 1;

    const float* base1 = a1 + (size_t)b * NPTS * DIMS;
    const float* base2 = a2 + (size_t)b * NPTS * DIMS;
    const float* samples = (pair & 1) ? base1 : base2;
    const float* refs    = ((pair & 1) ? base2 : base1) + (size_t)sp * RSPLIT * DIMS;

    const float qx = samples[q * 3 + 0];
    const float qy = samples[q * 3 + 1];
    const float qz = samples[q * 3 + 2];

    const __half2 qx2 = __floats2half2_rn(qx, qx);
    const __half2 qy2 = __floats2half2_rn(qy, qy);
    const __half2 qz2 = __floats2half2_rn(qz, qz);

    // tile: each thread converts 2 ref points (AoS fp32 -> half2 SoA)
    {
        const float* p = refs + (size_t)tid * 6;   // points 2*tid, 2*tid+1
        shX[tid] = __floats2half2_rn(p[0], p[3]);
        shY[tid] = __floats2half2_rn(p[1], p[4]);
        shZ[tid] = __floats2half2_rn(p[2], p[5]);
    }
    __syncthreads();

    const __half2 HMAXV = __float2half2_rn(65504.0f);
    __half2 am0 = HMAXV, am1 = HMAXV, am2 = HMAXV, am3 = HMAXV;

    const uint4* X = (const uint4*)shX;   // 64 uint4 = 256 half2 = 512 pts
    const uint4* Y = (const uint4*)shY;
    const uint4* Z = (const uint4*)shZ;

    #pragma unroll 4
    for (int j = 0; j < RSPLIT / 8; j++) {
        const uint4 xv = X[j], yv = Y[j], zv = Z[j];

        const __half2 ax0 = __habs2(__hsub2(qx2, h2_of(xv.x)));
        const __half2 ay0 = __habs2(__hsub2(qy2, h2_of(yv.x)));
        const __half2 az0 = __habs2(__hsub2(qz2, h2_of(zv.x)));
        am0 = __hmin2(am0, __hadd2(__hadd2(ax0, ay0), az0));

        const __half2 ax1 = __habs2(__hsub2(qx2, h2_of(xv.y)));
        const __half2 ay1 = __habs2(__hsub2(qy2, h2_of(yv.y)));
        const __half2 az1 = __habs2(__hsub2(qz2, h2_of(zv.y)));
        am1 = __hmin2(am1, __hadd2(__hadd2(ax1, ay1), az1));

        const __half2 ax2 = __habs2(__hsub2(qx2, h2_of(xv.z)));
        const __half2 ay2 = __habs2(__hsub2(qy2, h2_of(yv.z)));
        const __half2 az2 = __habs2(__hsub2(qz2, h2_of(zv.z)));
        am2 = __hmin2(am2, __hadd2(__hadd2(ax2, ay2), az2));

        const __half2 ax3 = __habs2(__hsub2(qx2, h2_of(xv.w)));
        const __half2 ay3 = __habs2(__hsub2(qy2, h2_of(yv.w)));
        const __half2 az3 = __habs2(__hsub2(qz2, h2_of(zv.w)));
        am3 = __hmin2(am3, __hadd2(__hadd2(ax3, ay3), az3));
    }

    const __half2 am = __hmin2(__hmin2(am0, am1), __hmin2(am2, am3));
    const float dmin = fminf(__low2float(am), __high2float(am));

    g_dmin[(size_t)(pair * NPTS + q) * SPLITS + sp] = dmin;

    // ---- ticketed tail: last FINB blocks finalize (proven R5 structure) ----
    __syncthreads();
    if (tid == 0) {
        __threadfence();
        s_ticket = atomicAdd(&g_ticket1, 1u);
    }
    __syncthreads();
    const unsigned int t = s_ticket;
    if (t < (unsigned)(nblocks - FINB)) return;

    const int rank = (int)t - (nblocks - FINB);

    if (tid == 0) {
        while (*((volatile unsigned int*)&g_ticket1) < (unsigned)nblocks) { }
    }
    __syncthreads();
    __threadfence();

    const float alpha = *alpha_p;
    const float beta  = *beta_p;
    const float delta = __powf(alpha, -1.0f / beta);

    const int per_blk = nq / FINB;               // 4096 queries
    const int qbase   = rank * per_blk;
    const float4* dm4 = (const float4*)g_dmin;   // 2 float4 per query

    float acc = 0.0f;
    #pragma unroll 2
    for (int i = tid; i < per_blk; i += THREADS) {
        const float4 d0 = dm4[(size_t)(qbase + i) * 2 + 0];
        const float4 d1 = dm4[(size_t)(qbase + i) * 2 + 1];
        float dmn = fminf(fminf(fminf(d0.x, d0.y), fminf(d0.z, d0.w)),
                          fminf(fminf(d1.x, d1.y), fminf(d1.z, d1.w)));
        const float sv = alpha * __powf(dmn, beta) + delta;
        acc += -sv * __expf(-sv);
    }

    #pragma unroll
    for (int o = 16; o > 0; o >>= 1)
        acc += __shfl_down_sync(0xffffffffu, acc, o);
    if ((tid & 31) == 0) red[tid >> 5] = acc;
    __syncthreads();

    if (tid == 0) {
        float v = 0.0f;
        #pragma unroll
        for (int w = 0; w < THREADS / 32; w++) v += red[w];
        g_fpart[rank] = v;
        __threadfence();
        const unsigned int t2 = atomicAdd(&g_ticket2, 1u);
        if (t2 == FINB - 1) {
            float total = 0.0f;
            #pragma unroll
            for (int r = 0; r < FINB; r++)
                total += *((volatile float*)&g_fpart[r]);
            out[0] = total * scale;
            g_ticket1 = 0;       // self-clean for graph replay
            g_ticket2 = 0;
        }
    }
}

extern "C" void kernel_launch(void* const* d_in, const int* in_sizes, int n_in,
                              void* d_out, int out_size)
{
    const float* a1    = (const float*)d_in[0];
    const float* a2    = (const float*)d_in[1];
    const float* alpha = (const float*)d_in[2];
    const float* beta  = (const float*)d_in[3];
    float* out = (float*)d_out;

    const int B  = in_sizes[0] / (NPTS * DIMS);
    const int nq = 2 * B * NPTS;
    const int nblocks = 2 * B * 16 * SPLITS;     // 1024 at B=4
    const float scale = 50.0f / (float)B;

    gps_kernel<<<nblocks, THREADS>>>(a1, a2, alpha, beta, out, nq, nblocks, scale);
}